// round 5
// baseline (speedup 1.0000x reference)
#include <cuda_runtime.h>
#include <cuda_bf16.h>

// Output [B,2] = [p, 1-p], p = sigmoid(evs . fc3_w + fc3_b); evs depends only
// on the 4-qubit circuit (q_params, q_basis). CNN branch is dead code.
//
// R4: flatten the critical path.
//  - all global loads (angles AND fc3 head) issued at kernel start, in parallel
//  - logit = b + sum_i prob_i * coef_i with per-lane coef = sum_w ±fc3_w[w]
//    computed BEFORE the sim finishes (off critical path)
//  - gate coefficients broadcast lane->warp via __shfl_sync (no smem table,
//    no syncwarp); final reduction is a 4-round shfl_xor butterfly
//  - 512 threads, one float4 (two output rows) per thread

__global__ __launch_bounds__(512, 1)
void qhbc_kernel(const float* __restrict__ q_params,  // [2,4,3]
                 const float* __restrict__ q_basis,   // [4,3]
                 const float* __restrict__ fc3_w,     // [1,4]
                 const float* __restrict__ fc3_b,     // [1]
                 float4* __restrict__ out4,           // [B/2] of (p,q,p,q)
                 int n4) {
    __shared__ float s_p;

    const int tid = threadIdx.x;

    if (tid < 32) {
        const int lane = tid;

        // ---- All global loads up front (max MLP, one latency exposure) ----
        // Gate g = lane (lanes 0..11 valid): wire w = g&3.
        const int w_ = lane & 3;
        const float* ang = (lane < 4) ? (q_basis + w_ * 3)
                                      : (q_params + (lane - 4) * 3);
        const float a0 = (lane < 12) ? ang[0] : 0.f;
        const float a1 = (lane < 12) ? ang[1] : 0.f;
        const float a2 = (lane < 12) ? ang[2] : 0.f;
        const float f0 = fc3_w[0], f1 = fc3_w[1], f2 = fc3_w[2], f3 = fc3_w[3];
        const float bias = fc3_b[0];

        // ---- Per-lane measurement coefficient (off the sim critical path) ----
        // wire0 -> bit3, wire1 -> bit2, wire2 -> bit1, wire3 -> bit0
        const float coef = ((lane & 8) ? -f0 : f0) + ((lane & 4) ? -f1 : f1)
                         + ((lane & 2) ? -f2 : f2) + ((lane & 1) ? -f3 : f3);

        // ---- Merged SU(2) gate U = Rz*Ry*Rx (each lane builds its own) ----
        float sa, ca, sb, cb, sc, cc;
        __sincosf(0.5f * a0, &sa, &ca);   // Rx
        __sincosf(0.5f * a1, &sb, &cb);   // Ry
        __sincosf(0.5f * a2, &sc, &cc);   // Rz
        const float m00r =  cb * ca, m00i =  sb * sa;
        const float m01r = -sb * ca, m01i = -cb * sa;
        const float gu0r = cc * m00r + sc * m00i;   // u0.r
        const float gu0i = cc * m00i - sc * m00r;   // u0.i
        const float gu1r = cc * m01r + sc * m01i;   // u1.r
        const float gu1i = cc * m01i - sc * m01r;   // u1.i

        // ---- 16-amplitude sim, one amp per lane (amp index = lane) ----
        float sr = (lane == 0) ? 1.f : 0.f;
        float si = 0.f;

#define GATE(g, w) {                                                         \
        const int s_ = 8 >> (w);                                             \
        const float u0r = __shfl_sync(0xffffffffu, gu0r, (g));               \
        const float u0i = __shfl_sync(0xffffffffu, gu0i, (g));               \
        const float u1r = __shfl_sync(0xffffffffu, gu1r, (g));               \
        const float u1i = __shfl_sync(0xffffffffu, gu1i, (g));               \
        const float sgn = (lane & s_) ? -1.f : 1.f;                          \
        const float Ai = sgn * u0i, Br = sgn * u1r;                          \
        const float pr = __shfl_xor_sync(0xffffffffu, sr, s_);               \
        const float pi = __shfl_xor_sync(0xffffffffu, si, s_);               \
        const float nr = u0r * sr - Ai * si + Br * pr - u1i * pi;            \
        const float ni = u0r * si + Ai * sr + Br * pi + u1i * pr;            \
        sr = nr; si = ni; }

#define CNOT(w) {                                                            \
        const int sc_ = 8 >> (w), sg_ = 4 >> (w);                            \
        const float pr = __shfl_xor_sync(0xffffffffu, sr, sg_);              \
        const float pi = __shfl_xor_sync(0xffffffffu, si, sg_);              \
        if (lane & sc_) { sr = pr; si = pi; } }

        // basis rotations
        GATE(0, 0) GATE(1, 1) GATE(2, 2) GATE(3, 3)
        // layer 0
        GATE(4, 0) GATE(5, 1) GATE(6, 2) GATE(7, 3)
        CNOT(0) CNOT(1) CNOT(2)
        // layer 1
        GATE(8, 0) GATE(9, 1) GATE(10, 2) GATE(11, 3)
        CNOT(0) CNOT(1) CNOT(2)

#undef GATE
#undef CNOT

        // ---- logit = bias + sum_{lanes 0..15} prob*coef via butterfly ----
        // xor masks 1,2,4,8 stay within lanes 0..15 (garbage in 16..31 never
        // reaches lane 0).
        float val = (sr * sr + si * si) * coef;
        val += __shfl_xor_sync(0xffffffffu, val, 1);
        val += __shfl_xor_sync(0xffffffffu, val, 2);
        val += __shfl_xor_sync(0xffffffffu, val, 4);
        val += __shfl_xor_sync(0xffffffffu, val, 8);

        if (lane == 0) {
            s_p = 1.f / (1.f + __expf(-(bias + val)));
        }
    }

    __syncthreads();

    // ---- Broadcast: 512 threads, one float4 (two rows) each ----
    const float p = s_p;
    const float q = 1.f - p;
    const float4 v = make_float4(p, q, p, q);
    for (int i = tid; i < n4; i += blockDim.x) {
        out4[i] = v;
    }
}

extern "C" void kernel_launch(void* const* d_in, const int* in_sizes, int n_in,
                              void* d_out, int out_size) {
    // metadata order: 0=x 1=conv1_w 2=conv1_b 3=conv2_w 4=conv2_b 5=fc1_w
    //                 6=fc1_b 7=fc2_w 8=fc2_b 9=q_params 10=q_basis 11=fc3_w 12=fc3_b
    const float* q_params = (const float*)d_in[9];
    const float* q_basis  = (const float*)d_in[10];
    const float* fc3_w    = (const float*)d_in[11];
    const float* fc3_b    = (const float*)d_in[12];
    float4* out4 = (float4*)d_out;
    const int n4 = out_size / 4;   // out_size = B*2 floats; 4 floats per float4

    qhbc_kernel<<<1, 512>>>(q_params, q_basis, fc3_w, fc3_b, out4, n4);
}

// round 6
// speedup vs baseline: 1.0386x; 1.0386x over previous
#include <cuda_runtime.h>
#include <cuda_bf16.h>

// Output [B,2] = [p, 1-p], p = sigmoid(evs . fc3_w + fc3_b); evs depends only
// on the 4-qubit circuit (q_params, q_basis). CNN branch is dead code.
//
// R5: zero-synchronization version.
//  - EVERY warp redundantly runs the 16-amplitude sim (it's ~20 shfl steps of
//    FMA work) and holds p in registers -> no shared memory, no __syncthreads,
//    no inter-warp dependency at all.
//  - Each warp then stores its own slice of the broadcast output immediately.
//  - Critical path per warp: global load -> sim -> STG. Nothing waits on
//    another warp.

__global__ __launch_bounds__(512, 1)
void qhbc_kernel(const float* __restrict__ q_params,  // [2,4,3]
                 const float* __restrict__ q_basis,   // [4,3]
                 const float* __restrict__ fc3_w,     // [1,4]
                 const float* __restrict__ fc3_b,     // [1]
                 float4* __restrict__ out4,           // [B/2] of (p,q,p,q)
                 int n4) {
    const int tid  = threadIdx.x;
    const int lane = tid & 31;

    // ---- All global loads up front (parallel across lanes; L2-broadcast
    //      across warps since every warp reads the same 13 words) ----
    const int w_ = lane & 3;
    const float* ang = (lane < 4) ? (q_basis + w_ * 3)
                                  : (q_params + (lane - 4) * 3);
    const float a0 = (lane < 12) ? ang[0] : 0.f;
    const float a1 = (lane < 12) ? ang[1] : 0.f;
    const float a2 = (lane < 12) ? ang[2] : 0.f;
    const float f0 = fc3_w[0], f1 = fc3_w[1], f2 = fc3_w[2], f3 = fc3_w[3];
    const float bias = fc3_b[0];

    // ---- Per-lane measurement coefficient (off the sim critical path) ----
    // wire0 -> bit3, wire1 -> bit2, wire2 -> bit1, wire3 -> bit0
    const float coef = ((lane & 8) ? -f0 : f0) + ((lane & 4) ? -f1 : f1)
                     + ((lane & 2) ? -f2 : f2) + ((lane & 1) ? -f3 : f3);

    // ---- Merged SU(2) gate U = Rz*Ry*Rx (each lane builds gate g = lane) ----
    float sa, ca, sb, cb, sc, cc;
    __sincosf(0.5f * a0, &sa, &ca);   // Rx
    __sincosf(0.5f * a1, &sb, &cb);   // Ry
    __sincosf(0.5f * a2, &sc, &cc);   // Rz
    const float m00r =  cb * ca, m00i =  sb * sa;
    const float m01r = -sb * ca, m01i = -cb * sa;
    const float gu0r = cc * m00r + sc * m00i;   // u0.r
    const float gu0i = cc * m00i - sc * m00r;   // u0.i
    const float gu1r = cc * m01r + sc * m01i;   // u1.r
    const float gu1i = cc * m01i - sc * m01r;   // u1.i

    // ---- 16-amplitude sim, one amp per lane (amp index = lane & 15) ----
    float sr = (lane == 0) ? 1.f : 0.f;
    float si = 0.f;

#define GATE(g, w) {                                                         \
    const int s_ = 8 >> (w);                                                 \
    const float u0r = __shfl_sync(0xffffffffu, gu0r, (g));                   \
    const float u0i = __shfl_sync(0xffffffffu, gu0i, (g));                   \
    const float u1r = __shfl_sync(0xffffffffu, gu1r, (g));                   \
    const float u1i = __shfl_sync(0xffffffffu, gu1i, (g));                   \
    const float sgn = (lane & s_) ? -1.f : 1.f;                              \
    const float Ai = sgn * u0i, Br = sgn * u1r;                              \
    const float pr = __shfl_xor_sync(0xffffffffu, sr, s_);                   \
    const float pi = __shfl_xor_sync(0xffffffffu, si, s_);                   \
    const float nr = u0r * sr - Ai * si + Br * pr - u1i * pi;                \
    const float ni = u0r * si + Ai * sr + Br * pi + u1i * pr;                \
    sr = nr; si = ni; }

#define CNOT(w) {                                                            \
    const int sc_ = 8 >> (w), sg_ = 4 >> (w);                                \
    const float pr = __shfl_xor_sync(0xffffffffu, sr, sg_);                  \
    const float pi = __shfl_xor_sync(0xffffffffu, si, sg_);                  \
    if (lane & sc_) { sr = pr; si = pi; } }

    // basis rotations
    GATE(0, 0) GATE(1, 1) GATE(2, 2) GATE(3, 3)
    // layer 0
    GATE(4, 0) GATE(5, 1) GATE(6, 2) GATE(7, 3)
    CNOT(0) CNOT(1) CNOT(2)
    // layer 1
    GATE(8, 0) GATE(9, 1) GATE(10, 2) GATE(11, 3)
    CNOT(0) CNOT(1) CNOT(2)

#undef GATE
#undef CNOT

    // ---- logit = bias + sum_{lanes 0..15} prob*coef (butterfly), then
    //      broadcast within the warp from lane 0. No smem, no barrier. ----
    float val = (sr * sr + si * si) * coef;
    val += __shfl_xor_sync(0xffffffffu, val, 1);
    val += __shfl_xor_sync(0xffffffffu, val, 2);
    val += __shfl_xor_sync(0xffffffffu, val, 4);
    val += __shfl_xor_sync(0xffffffffu, val, 8);
    const float logit = __shfl_sync(0xffffffffu, bias + val, 0);

    const float p = 1.f / (1.f + __expf(-logit));
    const float q = 1.f - p;
    const float4 v = make_float4(p, q, p, q);

    // ---- Each thread stores its own output slice immediately ----
    for (int i = tid; i < n4; i += blockDim.x) {
        out4[i] = v;
    }
}

extern "C" void kernel_launch(void* const* d_in, const int* in_sizes, int n_in,
                              void* d_out, int out_size) {
    // metadata order: 0=x 1=conv1_w 2=conv1_b 3=conv2_w 4=conv2_b 5=fc1_w
    //                 6=fc1_b 7=fc2_w 8=fc2_b 9=q_params 10=q_basis 11=fc3_w 12=fc3_b
    const float* q_params = (const float*)d_in[9];
    const float* q_basis  = (const float*)d_in[10];
    const float* fc3_w    = (const float*)d_in[11];
    const float* fc3_b    = (const float*)d_in[12];
    float4* out4 = (float4*)d_out;
    const int n4 = out_size / 4;   // out_size = B*2 floats; 4 floats per float4

    qhbc_kernel<<<1, 512>>>(q_params, q_basis, fc3_w, fc3_b, out4, n4);
}